// round 4
// baseline (speedup 1.0000x reference)
#include <cuda_runtime.h>
#include <math.h>

// Problem constants  (B,F,T,C = 8192, 256, 32, 100 — T is 32, NOT 100!)
#define BN 8192
#define FF 256
#define TT 32
#define NI 63
#define NL 64
#define CC 100
#define CP 128   // padded class dim

#define BM 64    // batch rows per CTA

// ---------------- scratch (device globals; no runtime allocation) ----------
__device__ float g_scalars[4];                 // [0] = inv_temp
__device__ float g_w[TT];                      // softmax(tree_weights)
__device__ float g_Mpad[TT * NL * CP];         // w[t]*softmax(leaf_logits/temp), padded

// ---------------- prep 0: single-thread, fully sequential -------------------
__global__ void prep0_kernel(const float* __restrict__ tw,
                             const float* __restrict__ log_temp) {
    if (threadIdx.x != 0 || blockIdx.x != 0) return;
    float temp = expf(log_temp[0]);
    temp = fminf(fmaxf(temp, 0.1f), 5.0f);
    g_scalars[0] = 1.0f / temp;

    float mx = -INFINITY;
    for (int t = 0; t < TT; t++) mx = fmaxf(mx, tw[t]);
    float sum = 0.0f;
    for (int t = 0; t < TT; t++) sum += expf(tw[t] - mx);
    float inv = 1.0f / sum;
    for (int t = 0; t < TT; t++) g_w[t] = expf(tw[t] - mx) * inv;
}

// ---------------- prep 1: M[t,l,c] = w[t]*softmax(leaf_logits/temp) ---------
__global__ void prep1_kernel(const float* __restrict__ leaf_logits) {
    __shared__ float sv[CP];
    __shared__ float s_mx, s_invsum, s_w;
    int blk = blockIdx.x;          // t*64 + l  (0 .. TT*64-1)
    int c = threadIdx.x;           // 0..127
    float v = (c < CC) ? leaf_logits[(size_t)blk * CC + c] * g_scalars[0]
                       : -INFINITY;
    sv[c] = v;
    __syncthreads();
    if (c == 0) {
        float mx = -INFINITY;
        for (int i = 0; i < CC; i++) mx = fmaxf(mx, sv[i]);
        float sum = 0.0f;
        for (int i = 0; i < CC; i++) sum += expf(sv[i] - mx);
        s_mx = mx;
        s_invsum = 1.0f / sum;
        s_w = g_w[blk >> 6];
    }
    __syncthreads();
    float r = (c < CC) ? s_w * expf(v - s_mx) * s_invsum : 0.0f;
    g_Mpad[(size_t)blk * CP + c] = r;
}

// ---------------- main fused kernel ----------------------------------------
// grid = 128 CTAs (one per 64-row batch tile); each loops all 32 trees and
// writes the final output directly.
// smem layout (floats):
//   xsT  [256][68]   0      .. 17408   (feature-major x tile)
//   wsT  [256][68]   17408  .. 34816   (feature-major W tile, node 63 pad)
//   plT  [64][65]    34816  .. 38976   (node-major split probs)
//   lpT  [64][65]    38976  .. 43136   (leaf-major leaf probs)
//   Ms   [64][128]   43136  .. 51328
//   sb   [64]        51328  .. 51392
#define SMEM_FLOATS 51392
#define SMEM_BYTES (SMEM_FLOATS * 4)

__global__ __launch_bounds__(256, 1)
void main_kernel(const float* __restrict__ x,
                 const float* __restrict__ W,
                 const float* __restrict__ split_bias,
                 float* __restrict__ out) {
    extern __shared__ float sm[];
    float* xsT = sm;
    float* wsT = sm + 17408;
    float* plT = sm + 34816;
    float* lpT = sm + 38976;
    float* Ms  = sm + 43136;
    float* sb  = sm + 51328;

    const int tid = threadIdx.x;
    const int tx = tid & 15;
    const int ty = tid >> 4;
    const int rowBase = blockIdx.x * BM;
    const float inv_temp = g_scalars[0];

    // ---- load + transpose x tile: xsT[k][row] = x[rowBase+row][k] ----
    {
        const int row = tid & 63;
        const int kc0 = tid >> 6;           // 0..3
        const float* xrow = x + (size_t)(rowBase + row) * FF;
#pragma unroll
        for (int m = 0; m < 16; m++) {
            int kc = kc0 + m * 4;
            float4 v = *(const float4*)(xrow + kc * 4);
            int kb = kc * 4;
            xsT[(kb + 0) * 68 + row] = v.x;
            xsT[(kb + 1) * 68 + row] = v.y;
            xsT[(kb + 2) * 68 + row] = v.z;
            xsT[(kb + 3) * 68 + row] = v.w;
        }
    }

    float outAcc[4][8];
#pragma unroll
    for (int i = 0; i < 4; i++)
#pragma unroll
        for (int j = 0; j < 8; j++) outAcc[i][j] = 0.0f;

    for (int t = 0; t < TT; t++) {
        __syncthreads();   // protect prev-iteration smem reads before overwrite

        // ---- load + transpose W tile: wsT[k][node] = W[t][node][k] ----
        {
            const int n = tid & 63;         // node 0..63 (63 = zero pad)
            const int kc0 = tid >> 6;
            const bool real = (n < NI);
            const float* wrow = W + ((size_t)t * NI + n) * FF;
#pragma unroll
            for (int m = 0; m < 16; m++) {
                int kc = kc0 + m * 4;
                float4 v = real ? *(const float4*)(wrow + kc * 4)
                                : make_float4(0.f, 0.f, 0.f, 0.f);
                int kb = kc * 4;
                wsT[(kb + 0) * 68 + n] = v.x;
                wsT[(kb + 1) * 68 + n] = v.y;
                wsT[(kb + 2) * 68 + n] = v.z;
                wsT[(kb + 3) * 68 + n] = v.w;
            }
        }
        // ---- load Ms[l][c] for tree t ----
        for (int idx = tid; idx < 64 * 32; idx += 256) {
            int l = idx >> 5;
            int c4 = (idx & 31) << 2;
            *(float4*)(Ms + l * CP + c4) =
                *(const float4*)(g_Mpad + ((size_t)t * NL + l) * CP + c4);
        }
        if (tid < 64) sb[tid] = (tid < NI) ? split_bias[t * NI + tid] : 0.0f;
        __syncthreads();

        // ---- phase 1: logits GEMM (64 rows x 64 nodes over K=256) ----
        float acc[4][4];
#pragma unroll
        for (int i = 0; i < 4; i++)
#pragma unroll
            for (int j = 0; j < 4; j++) acc[i][j] = 0.0f;

        const float* xp = xsT + ty * 4;
        const float* wp = wsT + tx * 4;
#pragma unroll 8
        for (int k = 0; k < 256; k++) {
            float4 a = *(const float4*)(xp + k * 68);
            float4 b = *(const float4*)(wp + k * 68);
            float av[4] = {a.x, a.y, a.z, a.w};
            float bv[4] = {b.x, b.y, b.z, b.w};
#pragma unroll
            for (int i = 0; i < 4; i++)
#pragma unroll
                for (int j = 0; j < 4; j++) acc[i][j] += av[i] * bv[j];
        }

        // sigmoid + write split probs (node-major)
#pragma unroll
        for (int j = 0; j < 4; j++) {
            int node = tx * 4 + j;
            float bias = sb[node];
#pragma unroll
            for (int i = 0; i < 4; i++) {
                float z = (acc[i][j] + bias) * inv_temp;
                float p = 1.0f / (1.0f + expf(-z));
                plT[node * 65 + ty * 4 + i] = p;
            }
        }
        __syncthreads();

        // ---- phase 2: leaf probs — reference heap climb ----
        for (int e = tid; e < NL * BM; e += 256) {
            int row = e & 63;
            int leaf = e >> 6;
            int node = leaf + NI;
            float p = 1.0f;
#pragma unroll
            for (int d = 0; d < 6; d++) {
                int parent = (node - 1) >> 1;
                float g = plT[parent * 65 + row];
                p *= ((node & 1) == 0) ? g : (1.0f - g);
                node = parent;
            }
            lpT[leaf * 65 + row] = p;
        }
        __syncthreads();

        // ---- phase 3: out += leafP @ M ----
#pragma unroll 4
        for (int l = 0; l < 64; l++) {
            float a0 = lpT[l * 65 + ty * 4 + 0];
            float a1 = lpT[l * 65 + ty * 4 + 1];
            float a2 = lpT[l * 65 + ty * 4 + 2];
            float a3 = lpT[l * 65 + ty * 4 + 3];
            float4 b0 = *(const float4*)(Ms + l * CP + tx * 8);
            float4 b1 = *(const float4*)(Ms + l * CP + tx * 8 + 4);
            float bv[8] = {b0.x, b0.y, b0.z, b0.w, b1.x, b1.y, b1.z, b1.w};
            float av[4] = {a0, a1, a2, a3};
#pragma unroll
            for (int i = 0; i < 4; i++)
#pragma unroll
                for (int j = 0; j < 8; j++) outAcc[i][j] += av[i] * bv[j];
        }
    }

    // ---- direct output write ----
#pragma unroll
    for (int i = 0; i < 4; i++) {
        int row = rowBase + ty * 4 + i;
        float* op = out + (size_t)row * CC;
#pragma unroll
        for (int j = 0; j < 8; j++) {
            int c = tx * 8 + j;
            if (c < CC) op[c] = outAcc[i][j];
        }
    }
}

// ---------------- launch -----------------------------------------------------
extern "C" void kernel_launch(void* const* d_in, const int* in_sizes, int n_in,
                              void* d_out, int out_size) {
    // Bind by element count (true sizes for T=32):
    //   x          8192*256    = 2097152
    //   split_w    32*63*256   = 516096
    //   split_bias 32*63       = 2016
    //   leaf_log   32*64*100   = 204800
    //   tree_w     32
    //   log_temp   1
    const float* x          = nullptr;
    const float* split_w    = nullptr;
    const float* split_bias = nullptr;
    const float* leaf_log   = nullptr;
    const float* tree_w     = nullptr;
    const float* log_temp   = nullptr;
    for (int i = 0; i < n_in; i++) {
        switch (in_sizes[i]) {
            case BN * FF:      x          = (const float*)d_in[i]; break;
            case TT * NI * FF: split_w    = (const float*)d_in[i]; break;
            case TT * NI:      split_bias = (const float*)d_in[i]; break;
            case TT * NL * CC: leaf_log   = (const float*)d_in[i]; break;
            case TT:           tree_w     = (const float*)d_in[i]; break;
            case 1:            log_temp   = (const float*)d_in[i]; break;
            default: break;
        }
    }
    if (!x)          x          = (const float*)d_in[0];
    if (!split_w)    split_w    = (const float*)d_in[1];
    if (!split_bias) split_bias = (const float*)d_in[2];
    if (!leaf_log)   leaf_log   = (const float*)d_in[3];
    if (!tree_w)     tree_w     = (const float*)d_in[4];
    if (!log_temp)   log_temp   = (const float*)d_in[5];
    float* out = (float*)d_out;

    prep0_kernel<<<1, 32>>>(tree_w, log_temp);
    prep1_kernel<<<TT * NL, CP>>>(leaf_log);

    cudaFuncSetAttribute(main_kernel,
                         cudaFuncAttributeMaxDynamicSharedMemorySize, SMEM_BYTES);
    main_kernel<<<BN / BM, 256, SMEM_BYTES>>>(x, split_w, split_bias, out);
}

// round 6
// speedup vs baseline: 1.2861x; 1.2861x over previous
#include <cuda_runtime.h>
#include <math.h>

// Problem constants  (B,F,T,C = 8192, 256, 32, 100)
#define BN 8192
#define FF 256
#define TT 32
#define NI 63
#define NL 64
#define CC 100
#define CPAD 128   // padded class dim

#define BM 64      // batch rows per CTA

// smem strides (floats) — ALL vector-accessed arrays must have stride ≡ 0 mod 4
#define XS 260     // xsT row stride  (1040 B, 16B-aligned; bank off 4)
#define WS 260     // wsT node stride
#define PLS 65     // plT row stride  (scalar access only)
#define LPS 68     // lpT row stride  (272 B, 16B-aligned; bank off 4)
#define MSS 68     // MsS class stride

// smem offsets (floats)
#define OFF_XS 0
#define OFF_WS (OFF_XS + 64 * XS)
#define OFF_PL (OFF_WS + 64 * WS)
#define OFF_LP (OFF_PL + 64 * PLS)
#define OFF_MS (OFF_LP + 64 * LPS)
#define OFF_SB (OFF_MS + CPAD * MSS)
#define SMEM_FLOATS (OFF_SB + 64)
#define SMEM_BYTES (SMEM_FLOATS * 4)

// packed f32x2 FMA (sm_103a FFMA2 — only reachable via PTX)
#define FMA2(acc, a, b) \
    asm("fma.rn.f32x2 %0, %1, %2, %3;" : "=l"(acc) : "l"(a), "l"(b), "l"(acc))

__device__ __forceinline__ float pair_sum(unsigned long long u) {
    return __uint_as_float((unsigned)u) + __uint_as_float((unsigned)(u >> 32));
}

// ---------------- scratch ----------------------------------------------------
__device__ float g_scalars[4];                  // [0] = inv_temp
__device__ float g_w[TT];                       // softmax(tree_weights)
__device__ float g_MsT[TT * CPAD * NL];         // transposed: [t][class][leaf]

// ---------------- prep 0 -----------------------------------------------------
__global__ void prep0_kernel(const float* __restrict__ tw,
                             const float* __restrict__ log_temp) {
    if (threadIdx.x != 0 || blockIdx.x != 0) return;
    float temp = expf(log_temp[0]);
    temp = fminf(fmaxf(temp, 0.1f), 5.0f);
    g_scalars[0] = 1.0f / temp;
    float mx = -INFINITY;
    for (int t = 0; t < TT; t++) mx = fmaxf(mx, tw[t]);
    float sum = 0.0f;
    for (int t = 0; t < TT; t++) sum += expf(tw[t] - mx);
    float inv = 1.0f / sum;
    for (int t = 0; t < TT; t++) g_w[t] = expf(tw[t] - mx) * inv;
}

// ---------------- prep 1: MsT[t][c][l] = w[t]*softmax(leaf_logits/temp)[c] --
__global__ void prep1_kernel(const float* __restrict__ leaf_logits) {
    __shared__ float sv[CPAD];
    __shared__ float s_mx, s_invsum, s_w;
    int blk = blockIdx.x;          // t*64 + l
    int t = blk >> 6;
    int l = blk & 63;
    int c = threadIdx.x;           // 0..127
    float v = (c < CC) ? leaf_logits[(size_t)blk * CC + c] * g_scalars[0]
                       : -INFINITY;
    sv[c] = v;
    __syncthreads();
    if (c == 0) {
        float mx = -INFINITY;
        for (int i = 0; i < CC; i++) mx = fmaxf(mx, sv[i]);
        float sum = 0.0f;
        for (int i = 0; i < CC; i++) sum += expf(sv[i] - mx);
        s_mx = mx;
        s_invsum = 1.0f / sum;
        s_w = g_w[t];
    }
    __syncthreads();
    float r = (c < CC) ? s_w * expf(v - s_mx) * s_invsum : 0.0f;
    g_MsT[((size_t)t * CPAD + c) * NL + l] = r;
}

// ---------------- main fused kernel -----------------------------------------
__global__ __launch_bounds__(256, 1)
void main_kernel(const float* __restrict__ x,
                 const float* __restrict__ W,
                 const float* __restrict__ split_bias,
                 float* __restrict__ out) {
    extern __shared__ float sm[];
    float* xsT = sm + OFF_XS;   // [row][k]      stride 260
    float* wsT = sm + OFF_WS;   // [node][k]     stride 260
    float* plT = sm + OFF_PL;   // [row][node]   stride 65 (scalar only)
    float* lpT = sm + OFF_LP;   // [row][leaf]   stride 68 (float4-read)
    float* MsS = sm + OFF_MS;   // [class][leaf] stride 68
    float* sb  = sm + OFF_SB;

    const int tid = threadIdx.x;
    const int tx = tid & 15;          // 0..15
    const int ty = tid >> 4;          // 0..15
    const int rowBase = blockIdx.x * BM;
    const float inv_temp = g_scalars[0];

    // ---- copy x tile (row-major, coalesced) ----
    {
        const int r = tid >> 2, q = tid & 3;
        const float* xrow = x + (size_t)(rowBase + r) * FF;
        float* dst = xsT + r * XS;
#pragma unroll
        for (int m = 0; m < 16; m++) {
            int c4 = (q + m * 4) * 4;
            *(float4*)(dst + c4) = *(const float4*)(xrow + c4);
        }
    }

    unsigned long long outAcc2[4][8];
#pragma unroll
    for (int i = 0; i < 4; i++)
#pragma unroll
        for (int j = 0; j < 8; j++) outAcc2[i][j] = 0ULL;

    for (int t = 0; t < TT; t++) {
        __syncthreads();   // protect prev-iteration smem before overwrite

        // ---- copy W tile (row-major; node 63 zero pad) ----
        {
            const int r = tid >> 2, q = tid & 3;
            const bool real = (r < NI);
            const float* wrow = W + ((size_t)t * NI + r) * FF;
            float* dst = wsT + r * WS;
#pragma unroll
            for (int m = 0; m < 16; m++) {
                int c4 = (q + m * 4) * 4;
                float4 v = real ? *(const float4*)(wrow + c4)
                                : make_float4(0.f, 0.f, 0.f, 0.f);
                *(float4*)(dst + c4) = v;
            }
        }
        // ---- copy MsT tile: MsS[c][l] ----
        for (int idx = tid; idx < CPAD * 16; idx += 256) {
            int c = idx >> 4;
            int l4 = (idx & 15) << 2;
            *(float4*)(MsS + c * MSS + l4) =
                *(const float4*)(g_MsT + ((size_t)t * CPAD + c) * NL + l4);
        }
        if (tid < 64) sb[tid] = (tid < NI) ? split_bias[t * NI + tid] : 0.0f;
        __syncthreads();

        // ---- phase 1: logits GEMM via FFMA2, K-paired accumulators ----
        unsigned long long acc2[4][4];
#pragma unroll
        for (int i = 0; i < 4; i++)
#pragma unroll
            for (int j = 0; j < 4; j++) acc2[i][j] = 0ULL;

#pragma unroll 2
        for (int k = 0; k < FF; k += 4) {
            unsigned long long a01[4], a23[4], b01[4], b23[4];
#pragma unroll
            for (int i = 0; i < 4; i++) {
                float4 v = *(const float4*)(xsT + (ty * 4 + i) * XS + k);
                a01[i] = *(const unsigned long long*)&v.x;
                a23[i] = *(const unsigned long long*)&v.z;
            }
#pragma unroll
            for (int j = 0; j < 4; j++) {
                float4 v = *(const float4*)(wsT + (tx + 16 * j) * WS + k);
                b01[j] = *(const unsigned long long*)&v.x;
                b23[j] = *(const unsigned long long*)&v.z;
            }
#pragma unroll
            for (int i = 0; i < 4; i++)
#pragma unroll
                for (int j = 0; j < 4; j++) {
                    FMA2(acc2[i][j], a01[i], b01[j]);
                    FMA2(acc2[i][j], a23[i], b23[j]);
                }
        }

        // sigmoid + write split probs plT[row][node]
#pragma unroll
        for (int j = 0; j < 4; j++) {
            int node = tx + 16 * j;
            float bias = sb[node];
#pragma unroll
            for (int i = 0; i < 4; i++) {
                float z = (pair_sum(acc2[i][j]) + bias) * inv_temp;
                float p = 1.0f / (1.0f + __expf(-z));
                plT[(ty * 4 + i) * PLS + node] = p;
            }
        }
        __syncthreads();

        // ---- phase 2: leaf probs (reference heap climb), lpT[row][leaf] ----
        // leaf = e&63 (consecutive within warp), row = e>>6 (constant in warp)
        for (int e = tid; e < NL * BM; e += 256) {
            int leaf = e & 63;
            int row = e >> 6;
            int node = leaf + NI;
            float p = 1.0f;
#pragma unroll
            for (int d = 0; d < 6; d++) {
                int parent = (node - 1) >> 1;
                float g = plT[row * PLS + parent];
                p *= ((node & 1) == 0) ? g : (1.0f - g);
                node = parent;
            }
            lpT[row * LPS + leaf] = p;
        }
        __syncthreads();

        // ---- phase 3: out += leafP @ M via FFMA2, L-paired accumulators ----
#pragma unroll 2
        for (int l = 0; l < NL; l += 4) {
            unsigned long long a01[4], a23[4];
#pragma unroll
            for (int i = 0; i < 4; i++) {
                float4 v = *(const float4*)(lpT + (ty * 4 + i) * LPS + l);
                a01[i] = *(const unsigned long long*)&v.x;
                a23[i] = *(const unsigned long long*)&v.z;
            }
#pragma unroll
            for (int j = 0; j < 8; j++) {
                float4 v = *(const float4*)(MsS + (tx + 16 * j) * MSS + l);
                unsigned long long b01 = *(const unsigned long long*)&v.x;
                unsigned long long b23 = *(const unsigned long long*)&v.z;
#pragma unroll
                for (int i = 0; i < 4; i++) {
                    FMA2(outAcc2[i][j], a01[i], b01);
                    FMA2(outAcc2[i][j], a23[i], b23);
                }
            }
        }
    }

    // ---- epilogue ----
#pragma unroll
    for (int i = 0; i < 4; i++) {
        int row = rowBase + ty * 4 + i;
        float* op = out + (size_t)row * CC;
#pragma unroll
        for (int j = 0; j < 8; j++) {
            int c = tx + 16 * j;
            if (c < CC) op[c] = pair_sum(outAcc2[i][j]);
        }
    }
}

// ---------------- launch -----------------------------------------------------
extern "C" void kernel_launch(void* const* d_in, const int* in_sizes, int n_in,
                              void* d_out, int out_size) {
    const float* x          = nullptr;   // 2097152
    const float* split_w    = nullptr;   // 516096
    const float* split_bias = nullptr;   // 2016
    const float* leaf_log   = nullptr;   // 204800
    const float* tree_w     = nullptr;   // 32
    const float* log_temp   = nullptr;   // 1
    for (int i = 0; i < n_in; i++) {
        switch (in_sizes[i]) {
            case BN * FF:      x          = (const float*)d_in[i]; break;
            case TT * NI * FF: split_w    = (const float*)d_in[i]; break;
            case TT * NI:      split_bias = (const float*)d_in[i]; break;
            case TT * NL * CC: leaf_log   = (const float*)d_in[i]; break;
            case TT:           tree_w     = (const float*)d_in[i]; break;
            case 1:            log_temp   = (const float*)d_in[i]; break;
            default: break;
        }
    }
    if (!x)          x          = (const float*)d_in[0];
    if (!split_w)    split_w    = (const float*)d_in[1];
    if (!split_bias) split_bias = (const float*)d_in[2];
    if (!leaf_log)   leaf_log   = (const float*)d_in[3];
    if (!tree_w)     tree_w     = (const float*)d_in[4];
    if (!log_temp)   log_temp   = (const float*)d_in[5];
    float* out = (float*)d_out;

    prep0_kernel<<<1, 32>>>(tree_w, log_temp);
    prep1_kernel<<<TT * NL, CPAD>>>(leaf_log);

    cudaFuncSetAttribute(main_kernel,
                         cudaFuncAttributeMaxDynamicSharedMemorySize, SMEM_BYTES);
    main_kernel<<<BN / BM, 256, SMEM_BYTES>>>(x, split_w, split_bias, out);
}